// round 4
// baseline (speedup 1.0000x reference)
#include <cuda_runtime.h>
#include <cuda_bf16.h>

// Problem constants
#define KSZ   15
#define PAD   10
#define L1    134            // R + 2*PAD - K + 1
#define MQ    17956          // L1*L1 queries
#define MPAD  18048          // 141 * 128
#define NMEM  16384
#define KDIM  225
#define KP2   114            // padded K/2  (K padded to 228)
#define CK2   19             // k2 per B chunk
#define NCH   6              // chunks (6*19 = 114)
#define MT    128            // queries per block
#define THREADS 512
#define GEMM_BLOCKS (MPAD/MT)            // 141
// A tile + double-buffered B chunk
#define SMEM_BYTES  ((KP2*MT + 2*CK2*MT) * (int)sizeof(float2))  // 155648

// -------- device scratch (static globals: no runtime allocation) ----------
__device__ float2 g_Xt2[KP2 * MPAD];    // [k2][q]  even/odd k packed
__device__ float2 g_memT2[KP2 * NMEM];  // [k2][j]  even/odd k packed
__device__ float  g_norms[NMEM];
__device__ int    g_idx[MPAD];
__device__ float  g_raw[64 * 64];

// -------- packed fp32x2 FMA (Blackwell FFMA2, PTX-only) -------------------
__device__ __forceinline__ unsigned long long fma2(unsigned long long a,
                                                   unsigned long long b,
                                                   unsigned long long c) {
    unsigned long long d;
    asm("fma.rn.f32x2 %0, %1, %2, %3;" : "=l"(d) : "l"(a), "l"(b), "l"(c));
    return d;
}

// ---------------------------------------------------------------------------
// Prep 1: build packed query planes Xt2[k2][q] from the 64x64 image.
// ---------------------------------------------------------------------------
__device__ __forceinline__ float sample_plane(const float* __restrict__ image,
                                              int r, int c, int k) {
    if (k >= KDIM) return 0.f;
    int i = k / KSZ, j = k - i * KSZ;
    int y = r + i - PAD, x = c + j - PAD;   // coords in the 128x128 upsampled img
    if ((unsigned)y < 128u && (unsigned)x < 128u)
        return image[(y >> 1) * 64 + (x >> 1)];
    return 0.f;
}

__global__ void prep_xt(const float* __restrict__ image) {
    int e = blockIdx.x * 256 + threadIdx.x;
    if (e >= KP2 * MPAD) return;
    int k2 = e / MPAD;
    int q  = e - k2 * MPAD;
    float2 v = make_float2(0.f, 0.f);
    if (q < MQ) {
        int r = q / L1, c = q - r * L1;
        v.x = sample_plane(image, r, c, 2 * k2);
        v.y = sample_plane(image, r, c, 2 * k2 + 1);
    }
    g_Xt2[e] = v;
}

// Prep 2: transpose+pack mem -> memT2[k2][j] (zeros beyond k=224)
__global__ void prep_memt(const float* __restrict__ mem) {
    int e = blockIdx.x * 256 + threadIdx.x;
    if (e >= KP2 * NMEM) return;
    int k2 = e >> 14;            // / 16384
    int j  = e & (NMEM - 1);
    int k0 = 2 * k2;
    float2 v;
    v.x = (k0     < KDIM) ? mem[j * KDIM + k0]     : 0.f;
    v.y = (k0 + 1 < KDIM) ? mem[j * KDIM + k0 + 1] : 0.f;
    g_memT2[e] = v;
}

// Prep 3: squared norms, one warp per mem row
__global__ void prep_norms(const float* __restrict__ mem) {
    int gw   = (blockIdx.x * blockDim.x + threadIdx.x) >> 5;
    int lane = threadIdx.x & 31;
    if (gw >= NMEM) return;
    const float* row = mem + gw * KDIM;
    float s = 0.f;
    for (int k = lane; k < KDIM; k += 32) { float v = row[k]; s += v * v; }
    #pragma unroll
    for (int o = 16; o; o >>= 1) s += __shfl_down_sync(0xffffffffu, s, o);
    if (lane == 0) g_norms[gw] = s;
}

// ---------------------------------------------------------------------------
// Fused GEMM + argmin.
// Block: 128 queries x all 16384 candidates (tiles of 128).
// Threads: 512 = 32(tx, N) x 16(ty = warp, M). Thread tile: 8(m) x 4(n).
// A tile resident in smem; B double-buffered via cp.async, 19-k2 chunks.
// ---------------------------------------------------------------------------
__global__ void __launch_bounds__(THREADS, 1) gemm_argmin() {
    extern __shared__ unsigned char smraw[];
    float2* As = (float2*)smraw;        // [KP2][128]
    float2* Bs = As + KP2 * MT;         // [2][CK2][128]

    const int tid = threadIdx.x;
    const int tx  = tid & 31;
    const int ty  = tid >> 5;           // 0..15
    const int qbase = blockIdx.x * MT;

    // Load the full A tile (128 queries x 114 packed-k) into smem.
    for (int i = tid; i < KP2 * MT; i += THREADS) {
        int k2 = i >> 7, m = i & 127;
        As[i] = g_Xt2[k2 * MPAD + qbase + m];
    }

    unsigned bs_base;
    {
        unsigned long long p = __cvta_generic_to_shared(Bs);
        bs_base = (unsigned)p;
    }

    float minv[8];
    int   mini[8];
    #pragma unroll
    for (int r = 0; r < 8; r++) { minv[r] = 3.4e38f; mini[r] = 0; }

    for (int jt = 0; jt < NMEM; jt += 128) {
        // async-preload chunk 0 into buffer 0
        {
            const int PAIRS = CK2 * 64;               // 16B units per chunk
            for (int p = tid; p < PAIRS; p += THREADS) {
                int row = p >> 6;
                int np  = (p & 63) << 1;
                const float2* src = &g_memT2[row * NMEM + jt + np];
                unsigned dst = bs_base + (unsigned)((row * MT + np) * sizeof(float2));
                asm volatile("cp.async.cg.shared.global [%0], [%1], 16;"
                             :: "r"(dst), "l"(src));
            }
            asm volatile("cp.async.commit_group;" ::: "memory");
        }

        unsigned long long acc[8][4];
        #pragma unroll
        for (int r = 0; r < 8; r++)
            #pragma unroll
            for (int c = 0; c < 4; c++) acc[r][c] = 0ull;

        for (int ch = 0; ch < NCH; ch++) {
            asm volatile("cp.async.wait_group 0;" ::: "memory");
            __syncthreads();   // copy(ch) visible; compute(ch-1) done everywhere

            if (ch + 1 < NCH) {  // prefetch next chunk into the other buffer
                const int PAIRS = CK2 * 64;
                int kbase = (ch + 1) * CK2;
                int bufo  = ((ch + 1) & 1) * CK2 * MT;
                for (int p = tid; p < PAIRS; p += THREADS) {
                    int row = p >> 6;
                    int np  = (p & 63) << 1;
                    const float2* src = &g_memT2[(kbase + row) * NMEM + jt + np];
                    unsigned dst = bs_base +
                        (unsigned)((bufo + row * MT + np) * sizeof(float2));
                    asm volatile("cp.async.cg.shared.global [%0], [%1], 16;"
                                 :: "r"(dst), "l"(src));
                }
                asm volatile("cp.async.commit_group;" ::: "memory");
            }

            const float2* Bbuf = Bs + (ch & 1) * CK2 * MT;

            #pragma unroll 2
            for (int kk = 0; kk < CK2; kk++) {
                const ulonglong2* Ar =
                    (const ulonglong2*)(As + (ch * CK2 + kk) * MT + ty * 8);
                const ulonglong2* Br =
                    (const ulonglong2*)(Bbuf + kk * MT);

                unsigned long long a[8], b[4];
                #pragma unroll
                for (int i = 0; i < 4; i++) {        // warp-uniform broadcast
                    ulonglong2 v = Ar[i];
                    a[2 * i] = v.x; a[2 * i + 1] = v.y;
                }
                {                                     // dense, conflict-free
                    ulonglong2 v0 = Br[tx];           // n = 2tx, 2tx+1
                    ulonglong2 v1 = Br[32 + tx];      // n = 64+2tx, 65+2tx
                    b[0] = v0.x; b[1] = v0.y; b[2] = v1.x; b[3] = v1.y;
                }
                #pragma unroll
                for (int r = 0; r < 8; r++)
                    #pragma unroll
                    for (int c = 0; c < 4; c++)
                        acc[r][c] = fma2(a[r], b[c], acc[r][c]);
            }
        }

        // distance + running argmin (j strictly ascending per thread -> '<'
        // keeps the first/lowest index, matching jnp.argmin)
        #pragma unroll
        for (int c = 0; c < 4; c++) {
            int j = jt + (c >> 1) * 64 + tx * 2 + (c & 1);
            float nrm = g_norms[j];
            #pragma unroll
            for (int r = 0; r < 8; r++) {
                float lo = __uint_as_float((unsigned)(acc[r][c]));
                float hi = __uint_as_float((unsigned)(acc[r][c] >> 32));
                float d  = nrm - 2.0f * (lo + hi);
                if (d < minv[r]) { minv[r] = d; mini[r] = j; }
            }
        }
        __syncthreads();   // before buffer-0 of the next jt is overwritten
    }

    // cross-thread (tx) argmin reduction per row, lexicographic tie-break
    float* sv = (float*)smraw;                 // [128][32]
    int*   si = (int*)(sv + 128 * 32);         // [128][32]
    #pragma unroll
    for (int r = 0; r < 8; r++) {
        int row = ty * 8 + r;
        sv[row * 32 + tx] = minv[r];
        si[row * 32 + tx] = mini[r];
    }
    __syncthreads();
    if (tid < 128) {
        float best = 3.4e38f; int bi = 0x7fffffff;
        for (int t = 0; t < 32; t++) {
            float v = sv[tid * 32 + t];
            int  id = si[tid * 32 + t];
            if (v < best || (v == best && id < bi)) { best = v; bi = id; }
        }
        g_idx[qbase + tid] = bi;
    }
}

// ---------------------------------------------------------------------------
// Reconstruction: only the 64x64 subsampled grid of the folded accumulator
// is ever observed: out_raw[a][b] = acc[2a+10][2b+10]
// ---------------------------------------------------------------------------
__global__ void recon(const float* __restrict__ mem) {
    int t = blockIdx.x * 256 + threadIdx.x;      // 0..4095
    if (t >= 4096) return;
    int a = t >> 6, b = t & 63;
    int y = 2 * a + PAD, x = 2 * b + PAD;
    float s = 0.f;
    #pragma unroll
    for (int i = 0; i < KSZ; i++) {
        int ry = y - i;
        if ((unsigned)ry >= (unsigned)L1) continue;
        int rowbase = ry * L1;
        #pragma unroll
        for (int j = 0; j < KSZ; j++) {
            int rx = x - j;
            if ((unsigned)rx >= (unsigned)L1) continue;
            s += mem[g_idx[rowbase + rx] * KDIM + i * KSZ + j];
        }
    }
    g_raw[t] = s;
}

// max-normalize (single block)
__global__ void normalize_out(float* __restrict__ out) {
    __shared__ float sm[256];
    int tid = threadIdx.x;
    float mx = -3.4e38f;
    for (int i = tid; i < 4096; i += 256) mx = fmaxf(mx, g_raw[i]);
    sm[tid] = mx;
    __syncthreads();
    for (int o = 128; o; o >>= 1) {
        if (tid < o) sm[tid] = fmaxf(sm[tid], sm[tid + o]);
        __syncthreads();
    }
    float m = sm[0];
    for (int i = tid; i < 4096; i += 256) out[i] = g_raw[i] / m;
}

// ---------------------------------------------------------------------------
extern "C" void kernel_launch(void* const* d_in, const int* in_sizes, int n_in,
                              void* d_out, int out_size) {
    const float* image = (const float*)d_in[0];   // 64*64
    const float* mem   = (const float*)d_in[1];   // 16384*225
    float* out = (float*)d_out;                   // 64*64

    cudaFuncSetAttribute(gemm_argmin,
                         cudaFuncAttributeMaxDynamicSharedMemorySize,
                         SMEM_BYTES);

    {
        int n = KP2 * MPAD;
        prep_xt<<<(n + 255) / 256, 256>>>(image);
    }
    {
        int n = KP2 * NMEM;
        prep_memt<<<(n + 255) / 256, 256>>>(mem);
    }
    prep_norms<<<(NMEM * 32) / 256, 256>>>(mem);

    gemm_argmin<<<GEMM_BLOCKS, THREADS, SMEM_BYTES>>>();

    recon<<<16, 256>>>(mem);
    normalize_out<<<1, 256>>>(out);
}

// round 5
// speedup vs baseline: 4.0209x; 4.0209x over previous
#include <cuda_runtime.h>
#include <cuda_bf16.h>

// Problem constants
#define KSZ   15
#define PAD   10
#define L1    134            // R + 2*PAD - K + 1
#define MQ    17956          // L1*L1 queries
#define NMEM  16384
#define KDIM  225
#define NC    67             // per-axis queries per parity class
#define MC    4489           // queries per class (67*67)
#define MCP   4608           // padded to 36*128
#define K2C   32             // compressed K = 64 -> 32 packed float2
#define BPC   36             // blocks per class
#define THREADS 512
#define GEMM_BLOCKS (4*BPC)  // 144
// A tile (32KB) + double-buffered B tile (2x32KB)
#define SMEM_BYTES  ((K2C*128 + 2*K2C*128) * (int)sizeof(float2))  // 98304

// -------- device scratch (static globals: no runtime allocation) ----------
__device__ float2 g_X2c[4 * K2C * MCP];    // [class][k2][qc]  packed slots
__device__ float2 g_m2[4 * K2C * NMEM];    // [class][k2][j]   compressed mem
__device__ float  g_norms[NMEM];
__device__ int    g_idx[MQ];
__device__ float  g_raw[64 * 64];

// -------- packed fp32x2 FMA (Blackwell FFMA2, PTX-only) -------------------
__device__ __forceinline__ unsigned long long fma2(unsigned long long a,
                                                   unsigned long long b,
                                                   unsigned long long c) {
    unsigned long long d;
    asm("fma.rn.f32x2 %0, %1, %2, %3;" : "=l"(d) : "l"(a), "l"(b), "l"(c));
    return d;
}

// ---------------------------------------------------------------------------
// Compressed-mem slot sum: m~[j][sy*8+sx] = sum of mem[j][i*15+jj] over the
// patch positions that map to source slot (sy,sx) for parity (py,px).
//   py==0: i in {2sy, 2sy+1};  py==1: i in {2sy-1, 2sy}   (clipped to [0,15))
// ---------------------------------------------------------------------------
__device__ __forceinline__ float slotsum(const float* __restrict__ row,
                                         int py, int px, int sy, int sx) {
    int i0 = py ? 2 * sy - 1 : 2 * sy;
    int i1 = i0 + 1;
    int j0 = px ? 2 * sx - 1 : 2 * sx;
    int j1 = j0 + 1;
    float s = 0.f;
    if ((unsigned)i0 < 15u) {
        if ((unsigned)j0 < 15u) s += row[i0 * KSZ + j0];
        if ((unsigned)j1 < 15u) s += row[i0 * KSZ + j1];
    }
    if ((unsigned)i1 < 15u) {
        if ((unsigned)j0 < 15u) s += row[i1 * KSZ + j0];
        if ((unsigned)j1 < 15u) s += row[i1 * KSZ + j1];
    }
    return s;
}

__global__ void prep_m2(const float* __restrict__ mem) {
    int e = blockIdx.x * 256 + threadIdx.x;
    if (e >= 4 * K2C * NMEM) return;
    int cls = e / (K2C * NMEM);
    int rem = e - cls * (K2C * NMEM);
    int k2  = rem >> 14;          // / 16384
    int j   = rem & (NMEM - 1);
    int py = cls >> 1, px = cls & 1;
    int s0 = 2 * k2;
    int sy = s0 >> 3, sx0 = s0 & 7;
    const float* row = mem + j * KDIM;
    float2 v;
    v.x = slotsum(row, py, px, sy, sx0);
    v.y = slotsum(row, py, px, sy, sx0 + 1);
    g_m2[e] = v;
}

// ---------------------------------------------------------------------------
// Compressed query vectors: x~[q][sy*8+sx] = image[by+sy][bx+sx] (0 if OOB),
// by = (r-10)>>1 (arithmetic shift = floor), r = py + 2a, c = px + 2b.
// ---------------------------------------------------------------------------
__global__ void prep_x2c(const float* __restrict__ image) {
    int e = blockIdx.x * 256 + threadIdx.x;
    if (e >= 4 * K2C * MCP) return;
    int cls = e / (K2C * MCP);
    int rem = e - cls * (K2C * MCP);
    int k2  = rem / MCP;
    int qc  = rem - k2 * MCP;
    float2 v = make_float2(0.f, 0.f);
    if (qc < MC) {
        int py = cls >> 1, px = cls & 1;
        int a = qc / NC, b = qc - a * NC;
        int r = py + 2 * a, c = px + 2 * b;
        int by = (r - PAD) >> 1, bx = (c - PAD) >> 1;
        int s0 = 2 * k2;
        int sy = s0 >> 3, sx0 = s0 & 7;
        int yy = by + sy;
        if ((unsigned)yy < 64u) {
            int x0 = bx + sx0, x1 = x0 + 1;
            if ((unsigned)x0 < 64u) v.x = image[yy * 64 + x0];
            if ((unsigned)x1 < 64u) v.y = image[yy * 64 + x1];
        }
    }
    g_X2c[e] = v;
}

// Prep: squared norms, one warp per mem row (exact, from original mem)
__global__ void prep_norms(const float* __restrict__ mem) {
    int gw   = (blockIdx.x * blockDim.x + threadIdx.x) >> 5;
    int lane = threadIdx.x & 31;
    if (gw >= NMEM) return;
    const float* row = mem + gw * KDIM;
    float s = 0.f;
    for (int k = lane; k < KDIM; k += 32) { float v = row[k]; s += v * v; }
    #pragma unroll
    for (int o = 16; o; o >>= 1) s += __shfl_down_sync(0xffffffffu, s, o);
    if (lane == 0) g_norms[gw] = s;
}

// ---------------------------------------------------------------------------
// Fused GEMM + argmin over compressed K=64.
// Block: 128 queries (one parity class) x 16384 candidates in tiles of 128.
// Threads: 512 = 32(tx, N) x 16(ty = warp, M). Thread tile: 8(m) x 4(n).
// A tile resident; B tile (32KB) double-buffered across j-tiles via cp.async.
// ---------------------------------------------------------------------------
__global__ void __launch_bounds__(THREADS, 1) gemm_argmin() {
    extern __shared__ unsigned char smraw[];
    float2* As = (float2*)smraw;        // [K2C][128]
    float2* Bs = As + K2C * 128;        // [2][K2C][128]

    const int tid = threadIdx.x;
    const int tx  = tid & 31;
    const int ty  = tid >> 5;           // 0..15
    const int cls   = blockIdx.x / BPC;
    const int qbase = (blockIdx.x - cls * BPC) * 128;

    // Load the full A tile (128 queries x 32 packed slots) into smem.
    for (int i = tid; i < K2C * 128; i += THREADS) {
        int k2 = i >> 7, m = i & 127;
        As[i] = g_X2c[(cls * K2C + k2) * MCP + qbase + m];
    }

    unsigned bs_base = (unsigned)__cvta_generic_to_shared(Bs);
    const int mbase = cls * K2C * NMEM;

    // async B-tile copy: 32 rows x 128 float2 = 2048 x 16B
    auto issueB = [&](int jt, int buf) {
        #pragma unroll
        for (int p = tid; p < K2C * 64; p += THREADS) {
            int row = p >> 6;
            int np  = (p & 63) << 1;
            const float2* src = &g_m2[mbase + row * NMEM + jt + np];
            unsigned dst = bs_base +
                (unsigned)((buf * K2C * 128 + row * 128 + np) * sizeof(float2));
            asm volatile("cp.async.cg.shared.global [%0], [%1], 16;"
                         :: "r"(dst), "l"(src));
        }
        asm volatile("cp.async.commit_group;" ::: "memory");
    };

    issueB(0, 0);

    float minv[8];
    int   mini[8];
    #pragma unroll
    for (int r = 0; r < 8; r++) { minv[r] = 3.4e38f; mini[r] = 0; }

    for (int jt = 0; jt < NMEM; jt += 128) {
        bool more = (jt + 128 < NMEM);
        if (more) issueB(jt + 128, ((jt >> 7) + 1) & 1);

        if (more) asm volatile("cp.async.wait_group 1;" ::: "memory");
        else      asm volatile("cp.async.wait_group 0;" ::: "memory");
        __syncthreads();   // current buf visible; As ready (first iter)

        const float2* Bbuf = Bs + ((jt >> 7) & 1) * K2C * 128;

        unsigned long long acc[8][4];
        #pragma unroll
        for (int r = 0; r < 8; r++)
            #pragma unroll
            for (int c = 0; c < 4; c++) acc[r][c] = 0ull;

        #pragma unroll 4
        for (int kk = 0; kk < K2C; kk++) {
            const ulonglong2* Ar =
                (const ulonglong2*)(As + kk * 128 + ty * 8);
            const ulonglong2* Br =
                (const ulonglong2*)(Bbuf + kk * 128);

            unsigned long long a[8], b[4];
            #pragma unroll
            for (int i = 0; i < 4; i++) {        // warp-uniform broadcast
                ulonglong2 v = Ar[i];
                a[2 * i] = v.x; a[2 * i + 1] = v.y;
            }
            {                                     // dense, conflict-free
                ulonglong2 v0 = Br[tx];           // n = 2tx, 2tx+1
                ulonglong2 v1 = Br[32 + tx];      // n = 64+2tx, 65+2tx
                b[0] = v0.x; b[1] = v0.y; b[2] = v1.x; b[3] = v1.y;
            }
            #pragma unroll
            for (int r = 0; r < 8; r++)
                #pragma unroll
                for (int c = 0; c < 4; c++)
                    acc[r][c] = fma2(a[r], b[c], acc[r][c]);
        }

        // distance + running argmin (j ascending per thread -> '<' keeps the
        // first/lowest index, matching jnp.argmin)
        #pragma unroll
        for (int c = 0; c < 4; c++) {
            int j = jt + (c >> 1) * 64 + tx * 2 + (c & 1);
            float nrm = g_norms[j];
            #pragma unroll
            for (int r = 0; r < 8; r++) {
                float lo = __uint_as_float((unsigned)(acc[r][c]));
                float hi = __uint_as_float((unsigned)(acc[r][c] >> 32));
                float d  = nrm - 2.0f * (lo + hi);
                if (d < minv[r]) { minv[r] = d; mini[r] = j; }
            }
        }
        __syncthreads();   // everyone done reading Bbuf before it is reloaded
    }

    // cross-thread (tx) argmin reduction per row, lexicographic tie-break
    float* sv = (float*)smraw;                 // [128][32]
    int*   si = (int*)(sv + 128 * 32);         // [128][32]
    #pragma unroll
    for (int r = 0; r < 8; r++) {
        int row = ty * 8 + r;
        sv[row * 32 + tx] = minv[r];
        si[row * 32 + tx] = mini[r];
    }
    __syncthreads();
    if (tid < 128) {
        float best = 3.4e38f; int bi = 0x7fffffff;
        for (int t = 0; t < 32; t++) {
            float v = sv[tid * 32 + t];
            int  id = si[tid * 32 + t];
            if (v < best || (v == best && id < bi)) { best = v; bi = id; }
        }
        int qc = qbase + tid;
        if (qc < MC) {
            int py = cls >> 1, px = cls & 1;
            int a = qc / NC, b = qc - a * NC;
            int q = (py + 2 * a) * L1 + (px + 2 * b);
            g_idx[q] = bi;
        }
    }
}

// ---------------------------------------------------------------------------
// Reconstruction: only the 64x64 subsampled grid of the folded accumulator
// is observed: out_raw[a][b] = acc[2a+10][2b+10]
//            = sum_{i,j} mem[ idx[(y-i)*134 + (x-j)] ][ i*15+j ]
// ---------------------------------------------------------------------------
__global__ void recon(const float* __restrict__ mem) {
    int t = blockIdx.x * 256 + threadIdx.x;      // 0..4095
    if (t >= 4096) return;
    int a = t >> 6, b = t & 63;
    int y = 2 * a + PAD, x = 2 * b + PAD;
    float s = 0.f;
    #pragma unroll
    for (int i = 0; i < KSZ; i++) {
        int ry = y - i;
        if ((unsigned)ry >= (unsigned)L1) continue;
        int rowbase = ry * L1;
        #pragma unroll
        for (int j = 0; j < KSZ; j++) {
            int rx = x - j;
            if ((unsigned)rx >= (unsigned)L1) continue;
            s += mem[g_idx[rowbase + rx] * KDIM + i * KSZ + j];
        }
    }
    g_raw[t] = s;
}

// max-normalize (single block)
__global__ void normalize_out(float* __restrict__ out) {
    __shared__ float sm[256];
    int tid = threadIdx.x;
    float mx = -3.4e38f;
    for (int i = tid; i < 4096; i += 256) mx = fmaxf(mx, g_raw[i]);
    sm[tid] = mx;
    __syncthreads();
    for (int o = 128; o; o >>= 1) {
        if (tid < o) sm[tid] = fmaxf(sm[tid], sm[tid + o]);
        __syncthreads();
    }
    float m = sm[0];
    for (int i = tid; i < 4096; i += 256) out[i] = g_raw[i] / m;
}

// ---------------------------------------------------------------------------
extern "C" void kernel_launch(void* const* d_in, const int* in_sizes, int n_in,
                              void* d_out, int out_size) {
    const float* image = (const float*)d_in[0];   // 64*64
    const float* mem   = (const float*)d_in[1];   // 16384*225
    float* out = (float*)d_out;                   // 64*64

    cudaFuncSetAttribute(gemm_argmin,
                         cudaFuncAttributeMaxDynamicSharedMemorySize,
                         SMEM_BYTES);

    {
        int n = 4 * K2C * MCP;
        prep_x2c<<<(n + 255) / 256, 256>>>(image);
    }
    {
        int n = 4 * K2C * NMEM;
        prep_m2<<<(n + 255) / 256, 256>>>(mem);
    }
    prep_norms<<<(NMEM * 32) / 256, 256>>>(mem);

    gemm_argmin<<<GEMM_BLOCKS, THREADS, SMEM_BYTES>>>();

    recon<<<16, 256>>>(mem);
    normalize_out<<<1, 256>>>(out);
}

// round 8
// speedup vs baseline: 5.5846x; 1.3889x over previous
#include <cuda_runtime.h>
#include <cuda_fp16.h>

// Problem constants
#define KSZ   15
#define PAD   10
#define L1    134
#define MQ    17956          // L1*L1 queries
#define NMEM  16384
#define KDIM  225
#define NC    67             // per-axis queries per parity class
#define MC    4489           // queries per class
#define KC    64             // compressed K (8x8 source window)
#define NT    128            // j-tiles of 128
#define BPC   36             // M-tiles (of 128) per class
#define GEMM_BLOCKS 144      // 4 classes * 36
#define GEMM_THREADS 256
#define TILE_B 16384         // bytes per (tile, split): 128 rows x 128B
// smem layout
#define SM_HN 0              // 16384 half-norms (64KB)
#define SM_A  65536          // 2 splits x 16KB
#define SM_B  98304          // 2 bufs x 2 splits x 16KB
#define GEMM_SMEM 163840

// -------- device scratch -----------------------------------------------------
__device__ __align__(16) unsigned char g_Ah[4 * BPC * 2 * TILE_B]; // fp16 A splits
__device__ __align__(16) unsigned char g_Bh[4 * NT * 2 * TILE_B];  // fp16 B splits
__device__ __align__(16) float g_m2f[4 * NMEM * KC];  // fp32 compressed mem
__device__ __align__(16) float g_norms[NMEM];         // HALF squared norms (0.5*|m|^2)
__device__ __align__(16) int4 g_cand4[MQ];            // top-2 per j-half (xy / zw)
__device__ int   g_idx[MQ];
__device__ float g_raw[64 * 64];

// -------- helpers ------------------------------------------------------------
__device__ __forceinline__ void split2h(float v, unsigned short& h0,
                                        unsigned short& h1) {
    __half a = __float2half_rn(v);
    float r = v - __half2float(a);
    __half b = __float2half_rn(r);
    h0 = __half_as_ushort(a);
    h1 = __half_as_ushort(b);
}

__device__ __forceinline__ void mma16816(float& d0, float& d1, float& d2, float& d3,
                                         unsigned a0, unsigned a1, unsigned a2,
                                         unsigned a3, unsigned b0, unsigned b1) {
    asm volatile(
        "mma.sync.aligned.m16n8k16.row.col.f32.f16.f16.f32 "
        "{%0,%1,%2,%3},{%4,%5,%6,%7},{%8,%9},{%0,%1,%2,%3};"
        : "+f"(d0), "+f"(d1), "+f"(d2), "+f"(d3)
        : "r"(a0), "r"(a1), "r"(a2), "r"(a3), "r"(b0), "r"(b1));
}

__device__ __forceinline__ void cpa16(unsigned dst, const void* src) {
    asm volatile("cp.async.cg.shared.global [%0], [%1], 16;" :: "r"(dst), "l"(src));
}
__device__ __forceinline__ void cpa_commit() {
    asm volatile("cp.async.commit_group;" ::: "memory");
}
__device__ __forceinline__ void cpa_wait1() {
    asm volatile("cp.async.wait_group 1;" ::: "memory");
}
__device__ __forceinline__ void cpa_wait0() {
    asm volatile("cp.async.wait_group 0;" ::: "memory");
}

// rank-before: larger score first; ties -> lower index
__device__ __forceinline__ bool rank_gt(float a, int ia, float b, int ib) {
    return (a > b) || (a == b && ia < ib);
}

// ---------------------------------------------------------------------------
// slot sum (validated in R4): patch positions mapping to source slot (sy,sx)
// for parity (py,px).
// ---------------------------------------------------------------------------
__device__ __forceinline__ float slotsum(const float* __restrict__ row,
                                         int py, int px, int sy, int sx) {
    int i0 = py ? 2 * sy - 1 : 2 * sy;
    int i1 = i0 + 1;
    int j0 = px ? 2 * sx - 1 : 2 * sx;
    int j1 = j0 + 1;
    float s = 0.f;
    if ((unsigned)i0 < 15u) {
        if ((unsigned)j0 < 15u) s += row[i0 * KSZ + j0];
        if ((unsigned)j1 < 15u) s += row[i0 * KSZ + j1];
    }
    if ((unsigned)i1 < 15u) {
        if ((unsigned)j0 < 15u) s += row[i1 * KSZ + j0];
        if ((unsigned)j1 < 15u) s += row[i1 * KSZ + j1];
    }
    return s;
}

// chunk-permuted in-row byte offset for logical k (0..63):
//   p=k&1, c=(k>>1)&3, h=(k>>3)&1, kk=k>>4, chunk=((c*2+h+row)&7)
//   byte = chunk*16 + kk*4 + p*2
__device__ __forceinline__ int kpos(int row, int k) {
    int c = (k >> 1) & 3, h = (k >> 3) & 1, kk = k >> 4;
    int chunk = ((c * 2 + h + row) & 7);
    return chunk * 16 + kk * 4 + (k & 1) * 2;
}

// ---------------------------------------------------------------------------
// Prep B: compressed mem -> 2 fp16 splits in chunk-permuted tiles + fp32 copy
// ---------------------------------------------------------------------------
__global__ void prep_Bh(const float* __restrict__ mem) {
    int e = blockIdx.x * 256 + threadIdx.x;
    if (e >= 4 * NMEM * 32) return;
    int k2  = e & 31;
    int j   = (e >> 5) & (NMEM - 1);
    int cls = e >> 19;
    int py = cls >> 1, px = cls & 1;
    int s0 = 2 * k2, sy = s0 >> 3, sx = s0 & 7;
    const float* row = mem + j * KDIM;
    float vx = slotsum(row, py, px, sy, sx);
    float vy = slotsum(row, py, px, sy, sx + 1);

    *(float2*)&g_m2f[((size_t)(cls * NMEM + j) << 6) + s0] = make_float2(vx, vy);

    unsigned short x0, x1, y0, y1;
    split2h(vx, x0, x1);
    split2h(vy, y0, y1);
    int r = j & 127;
    int off = kpos(r, s0);              // s0 even -> pair contiguous
    size_t base = (size_t)((cls * NT + (j >> 7)) * 2) * TILE_B + (size_t)r * 128;
    ushort2 v0; v0.x = x0; v0.y = y0;
    ushort2 v1; v1.x = x1; v1.y = y1;
    *(ushort2*)(g_Bh + base + off) = v0;
    *(ushort2*)(g_Bh + base + TILE_B + off) = v1;
}

// ---------------------------------------------------------------------------
// Prep A: compressed queries -> 2 fp16 splits in chunk-permuted tiles
// ---------------------------------------------------------------------------
__global__ void prep_Ah(const float* __restrict__ image) {
    int e = blockIdx.x * 256 + threadIdx.x;
    if (e >= 4 * BPC * 128 * 32) return;
    int k2  = e & 31;
    int r   = (e >> 5) & 127;
    int r1  = e >> 12;                  // cls*BPC + tile
    int tile = r1 % BPC;
    int cls  = r1 / BPC;
    int py = cls >> 1, px = cls & 1;
    float vx = 0.f, vy = 0.f;
    int qc = tile * 128 + r;
    int s0 = 2 * k2, sy = s0 >> 3, sx = s0 & 7;
    if (qc < MC) {
        int a = qc / NC, b = qc - a * NC;
        int by = ((py + 2 * a) - PAD) >> 1;
        int bx = ((px + 2 * b) - PAD) >> 1;
        int yy = by + sy;
        if ((unsigned)yy < 64u) {
            int x0i = bx + sx, x1i = x0i + 1;
            if ((unsigned)x0i < 64u) vx = image[yy * 64 + x0i];
            if ((unsigned)x1i < 64u) vy = image[yy * 64 + x1i];
        }
    }
    unsigned short x0, x1, y0, y1;
    split2h(vx, x0, x1);
    split2h(vy, y0, y1);
    int off = kpos(r, s0);
    size_t base = (size_t)(r1 * 2) * TILE_B + (size_t)r * 128;
    ushort2 v0; v0.x = x0; v0.y = y0;
    ushort2 v1; v1.x = x1; v1.y = y1;
    *(ushort2*)(g_Ah + base + off) = v0;
    *(ushort2*)(g_Ah + base + TILE_B + off) = v1;
}

// Prep: HALF squared norms (0.5*|m|^2), one warp per row
__global__ void prep_norms(const float* __restrict__ mem) {
    int gw   = (blockIdx.x * blockDim.x + threadIdx.x) >> 5;
    int lane = threadIdx.x & 31;
    if (gw >= NMEM) return;
    const float* row = mem + gw * KDIM;
    float s = 0.f;
    for (int k = lane; k < KDIM; k += 32) { float v = row[k]; s += v * v; }
    #pragma unroll
    for (int o = 16; o; o >>= 1) s += __shfl_down_sync(0xffffffffu, s, o);
    if (lane == 0) g_norms[gw] = 0.5f * s;
}

// ---------------------------------------------------------------------------
// Fused mma.sync GEMM + per-j-half top-2 of score = dot - 0.5*|m|^2.
// 144 blocks: (class, M-tile 128). 256 threads = 8 warps: 4(M) x 2(N).
// Warp tile 32x64; mma m16n8k16 fp16->fp32; K=64; 3 split products.
// wn=0 warps cover j%128 in [0,64), wn=1 in [64,128): each writes its own
// int2 half of g_cand4[q]; repair evaluates all 4 candidates exactly.
// ---------------------------------------------------------------------------
__global__ void __launch_bounds__(GEMM_THREADS, 1) gemm_argmin() {
    extern __shared__ unsigned char smc[];
    unsigned sb = (unsigned)__cvta_generic_to_shared(smc);
    const int tid = threadIdx.x;
    const int wid = tid >> 5, lane = tid & 31;
    const int wm = wid >> 1, wn = wid & 1;
    const int tu = lane >> 2, cfr = lane & 3;
    const int cls = blockIdx.x / BPC;
    const int tile_m = blockIdx.x - cls * BPC;

    // one-time copies: half-norms (64KB) + A splits (32KB) -> group 1
    {
        const uint4* ns = (const uint4*)g_norms;
        for (int i = tid; i < 4096; i += GEMM_THREADS)
            cpa16(sb + SM_HN + i * 16, ns + i);
        const uint4* as =
            (const uint4*)(g_Ah + (size_t)((cls * BPC + tile_m) * 2) * TILE_B);
        for (int i = tid; i < 2048; i += GEMM_THREADS)
            cpa16(sb + SM_A + i * 16, as + i);
        cpa_commit();
    }
    // B tile 0 -> group 2
    {
        const uint4* bs = (const uint4*)(g_Bh + (size_t)((cls * NT) * 2) * TILE_B);
        for (int i = tid; i < 2048; i += GEMM_THREADS)
            cpa16(sb + SM_B + i * 16, bs + i);
        cpa_commit();
    }

    const float2* hn2p = (const float2*)smc;               // half-norms
    float rb1[4], rb2[4];
    int   ri1[4], ri2[4];
    #pragma unroll
    for (int x = 0; x < 4; x++) {
        rb1[x] = -3.4e38f; rb2[x] = -3.4e38f;
        ri1[x] = 0x7fffffff; ri2[x] = 0x7fffffff;
    }

    const int sa_l[3] = {0, 0, 1};
    const int sb_l[3] = {0, 1, 0};

    for (int t = 0; t < NT; t++) {
        if (t + 1 < NT) {
            const uint4* bs =
                (const uint4*)(g_Bh + (size_t)((cls * NT + t + 1) * 2) * TILE_B);
            unsigned dst = sb + SM_B + ((t + 1) & 1) * 32768;
            for (int i = tid; i < 2048; i += GEMM_THREADS)
                cpa16(dst + i * 16, bs + i);
            cpa_commit();
            cpa_wait1();
        } else {
            cpa_wait0();
        }
        __syncthreads();   // buf t visible everywhere

        const uint4* Bbase = (const uint4*)(smc + SM_B + (t & 1) * 32768);

        float acc[2][8][4];
        #pragma unroll
        for (int mt = 0; mt < 2; mt++)
            #pragma unroll
            for (int nt = 0; nt < 8; nt++)
                #pragma unroll
                for (int q = 0; q < 4; q++) acc[mt][nt][q] = 0.f;

        #pragma unroll
        for (int pr = 0; pr < 3; pr++) {
            const uint4* Ap = (const uint4*)(smc + SM_A + sa_l[pr] * TILE_B);
            const uint4* Bp = Bbase + sb_l[pr] * 1024;

            uint4 ap[2][2][2];
            #pragma unroll
            for (int mt = 0; mt < 2; mt++)
                #pragma unroll
                for (int rr = 0; rr < 2; rr++)
                    #pragma unroll
                    for (int h = 0; h < 2; h++) {
                        int row = wm * 32 + mt * 16 + rr * 8 + tu;
                        ap[mt][rr][h] = Ap[row * 8 + ((cfr * 2 + h + row) & 7)];
                    }

            #pragma unroll
            for (int ng = 0; ng < 2; ng++) {
                uint4 bp[4][2];
                #pragma unroll
                for (int i = 0; i < 4; i++)
                    #pragma unroll
                    for (int h = 0; h < 2; h++) {
                        int n = wn * 64 + (ng * 4 + i) * 8 + tu;
                        bp[i][h] = Bp[n * 8 + ((cfr * 2 + h + n) & 7)];
                    }
                #pragma unroll
                for (int kk = 0; kk < 4; kk++) {
                    #pragma unroll
                    for (int mt = 0; mt < 2; mt++) {
                        unsigned a0 = ((const unsigned*)&ap[mt][0][0])[kk];
                        unsigned a1 = ((const unsigned*)&ap[mt][1][0])[kk];
                        unsigned a2 = ((const unsigned*)&ap[mt][0][1])[kk];
                        unsigned a3 = ((const unsigned*)&ap[mt][1][1])[kk];
                        #pragma unroll
                        for (int i = 0; i < 4; i++) {
                            int nt = ng * 4 + i;
                            mma16816(acc[mt][nt][0], acc[mt][nt][1],
                                     acc[mt][nt][2], acc[mt][nt][3],
                                     a0, a1, a2, a3,
                                     ((const unsigned*)&bp[i][0])[kk],
                                     ((const unsigned*)&bp[i][1])[kk]);
                        }
                    }
                }
            }
        }

        // epilogue: score = dot - hn[j]; running top-2 per row context
        int jt = t * 128;
        #pragma unroll
        for (int nt = 0; nt < 8; nt++) {
            float2 hn = hn2p[(jt >> 1) + wn * 32 + nt * 4 + cfr];
            int j0 = jt + wn * 64 + nt * 8 + cfr * 2;
            #pragma unroll
            for (int mt = 0; mt < 2; mt++) {
                #pragma unroll
                for (int rr = 0; rr < 2; rr++) {
                    int ctx = mt * 2 + rr;
                    float s0 = acc[mt][nt][rr * 2 + 0] - hn.x;
                    float s1 = acc[mt][nt][rr * 2 + 1] - hn.y;
                    if (s0 > rb1[ctx]) {
                        rb2[ctx] = rb1[ctx]; ri2[ctx] = ri1[ctx];
                        rb1[ctx] = s0; ri1[ctx] = j0;
                    } else if (s0 > rb2[ctx]) { rb2[ctx] = s0; ri2[ctx] = j0; }
                    if (s1 > rb1[ctx]) {
                        rb2[ctx] = rb1[ctx]; ri2[ctx] = ri1[ctx];
                        rb1[ctx] = s1; ri1[ctx] = j0 + 1;
                    } else if (s1 > rb2[ctx]) { rb2[ctx] = s1; ri2[ctx] = j0 + 1; }
                }
            }
        }
        __syncthreads();   // all warps done reading buf t before it is refilled
    }

    // merge top-2 across the 4 lanes (cfr groups) sharing each row
    #pragma unroll
    for (int ctx = 0; ctx < 4; ctx++) {
        #pragma unroll
        for (int m = 1; m <= 2; m <<= 1) {
            float ob1 = __shfl_xor_sync(0xffffffffu, rb1[ctx], m);
            int   oi1 = __shfl_xor_sync(0xffffffffu, ri1[ctx], m);
            float ob2 = __shfl_xor_sync(0xffffffffu, rb2[ctx], m);
            int   oi2 = __shfl_xor_sync(0xffffffffu, ri2[ctx], m);
            if (rank_gt(ob1, oi1, rb1[ctx], ri1[ctx])) {
                if (rank_gt(rb1[ctx], ri1[ctx], ob2, oi2)) {
                    rb2[ctx] = rb1[ctx]; ri2[ctx] = ri1[ctx];
                } else { rb2[ctx] = ob2; ri2[ctx] = oi2; }
                rb1[ctx] = ob1; ri1[ctx] = oi1;
            } else if (rank_gt(ob1, oi1, rb2[ctx], ri2[ctx])) {
                rb2[ctx] = ob1; ri2[ctx] = oi1;
            }
        }
    }
    // each wn-warp writes ITS j-half's top-2 into its own int2 slot
    if (cfr == 0) {
        #pragma unroll
        for (int ctx = 0; ctx < 4; ctx++) {
            int mt = ctx >> 1, rr = ctx & 1;
            int m_local = wm * 32 + mt * 16 + rr * 8 + tu;
            int qc = tile_m * 128 + m_local;
            if (qc < MC) {
                int py = cls >> 1, px = cls & 1;
                int a = qc / NC, b = qc - a * NC;
                int q = (py + 2 * a) * L1 + (px + 2 * b);
                int2 cd; cd.x = ri1[ctx]; cd.y = ri2[ctx];
                ((int2*)&g_cand4[q])[wn] = cd;
            }
        }
    }
}

// ---------------------------------------------------------------------------
// Repair: exact fp32 evaluation of the 4 candidates per query (top-2 from
// each j-half); semantics identical to the R4 kernel, which matched the
// reference argmin bit-for-bit.
// ---------------------------------------------------------------------------
__global__ void repair(const float* __restrict__ image) {
    int q = blockIdx.x * 256 + threadIdx.x;
    if (q >= MQ) return;
    int4 cd = g_cand4[q];
    int cands[4] = {cd.x, cd.y, cd.z, cd.w};
    int r = q / L1, c = q - r * L1;
    int cls = (r & 1) * 2 + (c & 1);
    int by = (r - PAD) >> 1, bx = (c - PAD) >> 1;
    float x[KC];
    #pragma unroll
    for (int s = 0; s < KC; s++) {
        int sy = s >> 3, sx = s & 7;
        int yy = by + sy, xx = bx + sx;
        x[s] = ((unsigned)yy < 64u && (unsigned)xx < 64u)
                   ? image[yy * 64 + xx] : 0.f;
    }
    float best = 3.4e38f; int bi = 0x7fffffff;
    #pragma unroll
    for (int ci = 0; ci < 4; ci++) {
        int cj = cands[ci];
        const float* mm = g_m2f + ((size_t)(cls * NMEM + cj) << 6);
        float d = 0.f;
        #pragma unroll
        for (int s = 0; s < KC; s++) d += x[s] * mm[s];
        d = g_norms[cj] - d;          // 0.5*(|m|^2 - 2 x.m)
        if (d < best || (d == best && cj < bi)) { best = d; bi = cj; }
    }
    g_idx[q] = bi;
}

// ---------------------------------------------------------------------------
// Reconstruction: out_raw[a][b] = acc[2a+10][2b+10]
// ---------------------------------------------------------------------------
__global__ void recon(const float* __restrict__ mem) {
    int t = blockIdx.x * 256 + threadIdx.x;      // 0..4095
    if (t >= 4096) return;
    int a = t >> 6, b = t & 63;
    int y = 2 * a + PAD, x = 2 * b + PAD;
    float s = 0.f;
    #pragma unroll
    for (int i = 0; i < KSZ; i++) {
        int ry = y - i;
        if ((unsigned)ry >= (unsigned)L1) continue;
        int rowbase = ry * L1;
        #pragma unroll
        for (int j = 0; j < KSZ; j++) {
            int rx = x - j;
            if ((unsigned)rx >= (unsigned)L1) continue;
            s += mem[g_idx[rowbase + rx] * KDIM + i * KSZ + j];
        }
    }
    g_raw[t] = s;
}

// max-normalize (single block)
__global__ void normalize_out(float* __restrict__ out) {
    __shared__ float smx[256];
    int tid = threadIdx.x;
    float mx = -3.4e38f;
    for (int i = tid; i < 4096; i += 256) mx = fmaxf(mx, g_raw[i]);
    smx[tid] = mx;
    __syncthreads();
    for (int o = 128; o; o >>= 1) {
        if (tid < o) smx[tid] = fmaxf(smx[tid], smx[tid + o]);
        __syncthreads();
    }
    float m = smx[0];
    for (int i = tid; i < 4096; i += 256) out[i] = g_raw[i] / m;
}

// ---------------------------------------------------------------------------
extern "C" void kernel_launch(void* const* d_in, const int* in_sizes, int n_in,
                              void* d_out, int out_size) {
    const float* image = (const float*)d_in[0];   // 64*64
    const float* mem   = (const float*)d_in[1];   // 16384*225
    float* out = (float*)d_out;                   // 64*64

    cudaFuncSetAttribute(gemm_argmin,
                         cudaFuncAttributeMaxDynamicSharedMemorySize,
                         GEMM_SMEM);

    {
        int n = 4 * BPC * 128 * 32;
        prep_Ah<<<(n + 255) / 256, 256>>>(image);
    }
    {
        int n = 4 * NMEM * 32;
        prep_Bh<<<(n + 255) / 256, 256>>>(mem);
    }
    prep_norms<<<(NMEM * 32) / 256, 256>>>(mem);

    gemm_argmin<<<GEMM_BLOCKS, GEMM_THREADS, GEMM_SMEM>>>();

    repair<<<(MQ + 255) / 256, 256>>>(image);
    recon<<<16, 256>>>(mem);
    normalize_out<<<1, 256>>>(out);
}

// round 9
// speedup vs baseline: 9.6194x; 1.7225x over previous
#include <cuda_runtime.h>
#include <cuda_fp16.h>

// Problem constants
#define KSZ   15
#define PAD   10
#define L1    134
#define MQ    17956          // L1*L1 queries
#define NMEM  16384
#define KDIM  225
#define NC    67             // per-axis queries per parity class
#define MC    4489           // queries per class
#define KC    64             // compressed K (8x8 source window)
#define NT    128            // j-tiles of 128
#define BPC   36             // M-tiles (of 128) per class
#define GEMM_BLOCKS 144      // 4 classes * 36
#define GEMM_THREADS 256
#define TILE_B 16384         // bytes per (tile, split): 128 rows x 128B
// smem layout
#define SM_HN 0              // 16384 half-norms (64KB)
#define SM_A  65536          // 2 splits x 16KB
#define SM_B  98304          // 2 bufs x 2 splits x 16KB
#define GEMM_SMEM 163840

// -------- device scratch -----------------------------------------------------
__device__ __align__(16) unsigned char g_Ah[4 * BPC * 2 * TILE_B]; // fp16 A splits
__device__ __align__(16) unsigned char g_Bh[4 * NT * 2 * TILE_B];  // fp16 B splits
__device__ __align__(16) float g_m2f[4 * NMEM * KC];  // fp32 compressed mem
__device__ __align__(16) float g_norms[NMEM];         // HALF squared norms (0.5*|m|^2)
__device__ __align__(16) int4 g_cand4[MQ];            // top-2 per j-half (xy / zw)
__device__ int   g_idx[MQ];
__device__ float g_raw[64 * 64];

// -------- helpers ------------------------------------------------------------
__device__ __forceinline__ void split2h(float v, unsigned short& h0,
                                        unsigned short& h1) {
    __half a = __float2half_rn(v);
    float r = v - __half2float(a);
    __half b = __float2half_rn(r);
    h0 = __half_as_ushort(a);
    h1 = __half_as_ushort(b);
}

__device__ __forceinline__ void mma16816(float& d0, float& d1, float& d2, float& d3,
                                         unsigned a0, unsigned a1, unsigned a2,
                                         unsigned a3, unsigned b0, unsigned b1) {
    asm volatile(
        "mma.sync.aligned.m16n8k16.row.col.f32.f16.f16.f32 "
        "{%0,%1,%2,%3},{%4,%5,%6,%7},{%8,%9},{%0,%1,%2,%3};"
        : "+f"(d0), "+f"(d1), "+f"(d2), "+f"(d3)
        : "r"(a0), "r"(a1), "r"(a2), "r"(a3), "r"(b0), "r"(b1));
}

__device__ __forceinline__ void cpa16(unsigned dst, const void* src) {
    asm volatile("cp.async.cg.shared.global [%0], [%1], 16;" :: "r"(dst), "l"(src));
}
__device__ __forceinline__ void cpa_commit() {
    asm volatile("cp.async.commit_group;" ::: "memory");
}
__device__ __forceinline__ void cpa_wait1() {
    asm volatile("cp.async.wait_group 1;" ::: "memory");
}
__device__ __forceinline__ void cpa_wait0() {
    asm volatile("cp.async.wait_group 0;" ::: "memory");
}

// rank-before: larger score first; ties -> lower index
__device__ __forceinline__ bool rank_gt(float a, int ia, float b, int ib) {
    return (a > b) || (a == b && ia < ib);
}

// ---------------------------------------------------------------------------
// slot sum (validated in R4): patch positions mapping to source slot (sy,sx)
// for parity (py,px).
// ---------------------------------------------------------------------------
__device__ __forceinline__ float slotsum(const float* __restrict__ row,
                                         int py, int px, int sy, int sx) {
    int i0 = py ? 2 * sy - 1 : 2 * sy;
    int i1 = i0 + 1;
    int j0 = px ? 2 * sx - 1 : 2 * sx;
    int j1 = j0 + 1;
    float s = 0.f;
    if ((unsigned)i0 < 15u) {
        if ((unsigned)j0 < 15u) s += row[i0 * KSZ + j0];
        if ((unsigned)j1 < 15u) s += row[i0 * KSZ + j1];
    }
    if ((unsigned)i1 < 15u) {
        if ((unsigned)j0 < 15u) s += row[i1 * KSZ + j0];
        if ((unsigned)j1 < 15u) s += row[i1 * KSZ + j1];
    }
    return s;
}

// chunk-permuted in-row byte offset for logical k (0..63)
__device__ __forceinline__ int kpos(int row, int k) {
    int c = (k >> 1) & 3, h = (k >> 3) & 1, kk = k >> 4;
    int chunk = ((c * 2 + h + row) & 7);
    return chunk * 16 + kk * 4 + (k & 1) * 2;
}

// ---------------------------------------------------------------------------
// Prep B: compressed mem -> 2 fp16 splits in chunk-permuted tiles + fp32 copy
// ---------------------------------------------------------------------------
__global__ void prep_Bh(const float* __restrict__ mem) {
    int e = blockIdx.x * 256 + threadIdx.x;
    if (e >= 4 * NMEM * 32) return;
    int k2  = e & 31;
    int j   = (e >> 5) & (NMEM - 1);
    int cls = e >> 19;
    int py = cls >> 1, px = cls & 1;
    int s0 = 2 * k2, sy = s0 >> 3, sx = s0 & 7;
    const float* row = mem + j * KDIM;
    float vx = slotsum(row, py, px, sy, sx);
    float vy = slotsum(row, py, px, sy, sx + 1);

    *(float2*)&g_m2f[((size_t)(cls * NMEM + j) << 6) + s0] = make_float2(vx, vy);

    unsigned short x0, x1, y0, y1;
    split2h(vx, x0, x1);
    split2h(vy, y0, y1);
    int r = j & 127;
    int off = kpos(r, s0);
    size_t base = (size_t)((cls * NT + (j >> 7)) * 2) * TILE_B + (size_t)r * 128;
    ushort2 v0; v0.x = x0; v0.y = y0;
    ushort2 v1; v1.x = x1; v1.y = y1;
    *(ushort2*)(g_Bh + base + off) = v0;
    *(ushort2*)(g_Bh + base + TILE_B + off) = v1;
}

// ---------------------------------------------------------------------------
// Prep A: compressed queries -> 2 fp16 splits in chunk-permuted tiles
// ---------------------------------------------------------------------------
__global__ void prep_Ah(const float* __restrict__ image) {
    int e = blockIdx.x * 256 + threadIdx.x;
    if (e >= 4 * BPC * 128 * 32) return;
    int k2  = e & 31;
    int r   = (e >> 5) & 127;
    int r1  = e >> 12;                  // cls*BPC + tile
    int tile = r1 % BPC;
    int cls  = r1 / BPC;
    int py = cls >> 1, px = cls & 1;
    float vx = 0.f, vy = 0.f;
    int qc = tile * 128 + r;
    int s0 = 2 * k2, sy = s0 >> 3, sx = s0 & 7;
    if (qc < MC) {
        int a = qc / NC, b = qc - a * NC;
        int by = ((py + 2 * a) - PAD) >> 1;
        int bx = ((px + 2 * b) - PAD) >> 1;
        int yy = by + sy;
        if ((unsigned)yy < 64u) {
            int x0i = bx + sx, x1i = x0i + 1;
            if ((unsigned)x0i < 64u) vx = image[yy * 64 + x0i];
            if ((unsigned)x1i < 64u) vy = image[yy * 64 + x1i];
        }
    }
    unsigned short x0, x1, y0, y1;
    split2h(vx, x0, x1);
    split2h(vy, y0, y1);
    int off = kpos(r, s0);
    size_t base = (size_t)(r1 * 2) * TILE_B + (size_t)r * 128;
    ushort2 v0; v0.x = x0; v0.y = y0;
    ushort2 v1; v1.x = x1; v1.y = y1;
    *(ushort2*)(g_Ah + base + off) = v0;
    *(ushort2*)(g_Ah + base + TILE_B + off) = v1;
}

// Prep: HALF squared norms (0.5*|m|^2), one warp per row
__global__ void prep_norms(const float* __restrict__ mem) {
    int gw   = (blockIdx.x * blockDim.x + threadIdx.x) >> 5;
    int lane = threadIdx.x & 31;
    if (gw >= NMEM) return;
    const float* row = mem + gw * KDIM;
    float s = 0.f;
    for (int k = lane; k < KDIM; k += 32) { float v = row[k]; s += v * v; }
    #pragma unroll
    for (int o = 16; o; o >>= 1) s += __shfl_down_sync(0xffffffffu, s, o);
    if (lane == 0) g_norms[gw] = 0.5f * s;
}

// ---------------------------------------------------------------------------
// Fused mma.sync GEMM + per-j-half top-2 of score = dot - 0.5*|m|^2.
// 144 blocks: (class, M-tile 128). 256 threads = 8 warps: 4(M) x 2(N).
// Warp tile 32x64; mma m16n8k16 fp16->fp32; K=64; 3 split products.
// A fragments hoisted out of the j-loop (tile-constant); B0 frags reused
// across both A-split products. Epilogue: per-ctx fmax tree + rare indexed
// rescan; per-half top-2 -> exact fp32 repair.
// ---------------------------------------------------------------------------
__global__ void __launch_bounds__(GEMM_THREADS, 1) gemm_argmin() {
    extern __shared__ unsigned char smc[];
    unsigned sb = (unsigned)__cvta_generic_to_shared(smc);
    const int tid = threadIdx.x;
    const int wid = tid >> 5, lane = tid & 31;
    const int wm = wid >> 1, wn = wid & 1;
    const int tu = lane >> 2, cfr = lane & 3;
    const int cls = blockIdx.x / BPC;
    const int tile_m = blockIdx.x - cls * BPC;

    // chunk permutation offsets (thread-constant: row&7 == n&7 == tu)
    const int ch0 = (cfr * 2 + 0 + tu) & 7;
    const int ch1 = (cfr * 2 + 1 + tu) & 7;

    // one-time copies: half-norms (64KB) + A splits (32KB) -> group 1
    {
        const uint4* ns = (const uint4*)g_norms;
        for (int i = tid; i < 4096; i += GEMM_THREADS)
            cpa16(sb + SM_HN + i * 16, ns + i);
        const uint4* as =
            (const uint4*)(g_Ah + (size_t)((cls * BPC + tile_m) * 2) * TILE_B);
        for (int i = tid; i < 2048; i += GEMM_THREADS)
            cpa16(sb + SM_A + i * 16, as + i);
        cpa_commit();
    }
    // B tile 0 -> group 2
    {
        const uint4* bs = (const uint4*)(g_Bh + (size_t)((cls * NT) * 2) * TILE_B);
        for (int i = tid; i < 2048; i += GEMM_THREADS)
            cpa16(sb + SM_B + i * 16, bs + i);
        cpa_commit();
    }

    // wait for group 1 (norms + A), then hoist A fragments into registers
    cpa_wait1();
    __syncthreads();
    uint4 a0f[2][2][2], a1f[2][2][2];
    {
        const uint4* Ap0 = (const uint4*)(smc + SM_A);
        const uint4* Ap1 = (const uint4*)(smc + SM_A + TILE_B);
        #pragma unroll
        for (int mt = 0; mt < 2; mt++)
            #pragma unroll
            for (int rr = 0; rr < 2; rr++) {
                int row = wm * 32 + mt * 16 + rr * 8 + tu;
                a0f[mt][rr][0] = Ap0[row * 8 + ch0];
                a0f[mt][rr][1] = Ap0[row * 8 + ch1];
                a1f[mt][rr][0] = Ap1[row * 8 + ch0];
                a1f[mt][rr][1] = Ap1[row * 8 + ch1];
            }
    }

    const float2* hn2p = (const float2*)smc;               // half-norms
    float rb1[4], rb2[4];
    int   ri1[4], ri2[4];
    #pragma unroll
    for (int x = 0; x < 4; x++) {
        rb1[x] = -3.4e38f; rb2[x] = -3.4e38f;
        ri1[x] = 0x7fffffff; ri2[x] = 0x7fffffff;
    }

    for (int t = 0; t < NT; t++) {
        if (t + 1 < NT) {
            const uint4* bs =
                (const uint4*)(g_Bh + (size_t)((cls * NT + t + 1) * 2) * TILE_B);
            unsigned dst = sb + SM_B + ((t + 1) & 1) * 32768;
            for (int i = tid; i < 2048; i += GEMM_THREADS)
                cpa16(dst + i * 16, bs + i);
            cpa_commit();
            cpa_wait1();
        } else {
            cpa_wait0();
        }
        __syncthreads();   // buf t visible everywhere

        const uint4* Bbase = (const uint4*)(smc + SM_B + (t & 1) * 32768);

        float acc[2][8][4];
        #pragma unroll
        for (int mt = 0; mt < 2; mt++)
            #pragma unroll
            for (int nt = 0; nt < 8; nt++)
                #pragma unroll
                for (int q = 0; q < 4; q++) acc[mt][nt][q] = 0.f;

        // ---- B split 0: products A0*B0 and A1*B0 (B frags loaded once) ----
        #pragma unroll
        for (int ng = 0; ng < 2; ng++) {
            uint4 bp[4][2];
            #pragma unroll
            for (int i = 0; i < 4; i++) {
                int n = wn * 64 + (ng * 4 + i) * 8 + tu;
                bp[i][0] = Bbase[n * 8 + ch0];
                bp[i][1] = Bbase[n * 8 + ch1];
            }
            #pragma unroll
            for (int kk = 0; kk < 4; kk++)
                #pragma unroll
                for (int mt = 0; mt < 2; mt++) {
                    unsigned a0 = ((const unsigned*)&a0f[mt][0][0])[kk];
                    unsigned a1 = ((const unsigned*)&a0f[mt][1][0])[kk];
                    unsigned a2 = ((const unsigned*)&a0f[mt][0][1])[kk];
                    unsigned a3 = ((const unsigned*)&a0f[mt][1][1])[kk];
                    #pragma unroll
                    for (int i = 0; i < 4; i++) {
                        int nt = ng * 4 + i;
                        mma16816(acc[mt][nt][0], acc[mt][nt][1],
                                 acc[mt][nt][2], acc[mt][nt][3],
                                 a0, a1, a2, a3,
                                 ((const unsigned*)&bp[i][0])[kk],
                                 ((const unsigned*)&bp[i][1])[kk]);
                    }
                }
            #pragma unroll
            for (int kk = 0; kk < 4; kk++)
                #pragma unroll
                for (int mt = 0; mt < 2; mt++) {
                    unsigned a0 = ((const unsigned*)&a1f[mt][0][0])[kk];
                    unsigned a1 = ((const unsigned*)&a1f[mt][1][0])[kk];
                    unsigned a2 = ((const unsigned*)&a1f[mt][0][1])[kk];
                    unsigned a3 = ((const unsigned*)&a1f[mt][1][1])[kk];
                    #pragma unroll
                    for (int i = 0; i < 4; i++) {
                        int nt = ng * 4 + i;
                        mma16816(acc[mt][nt][0], acc[mt][nt][1],
                                 acc[mt][nt][2], acc[mt][nt][3],
                                 a0, a1, a2, a3,
                                 ((const unsigned*)&bp[i][0])[kk],
                                 ((const unsigned*)&bp[i][1])[kk]);
                    }
                }
        }
        // ---- B split 1: product A0*B1 ----
        #pragma unroll
        for (int ng = 0; ng < 2; ng++) {
            uint4 bp[4][2];
            #pragma unroll
            for (int i = 0; i < 4; i++) {
                int n = wn * 64 + (ng * 4 + i) * 8 + tu;
                bp[i][0] = Bbase[1024 + n * 8 + ch0];
                bp[i][1] = Bbase[1024 + n * 8 + ch1];
            }
            #pragma unroll
            for (int kk = 0; kk < 4; kk++)
                #pragma unroll
                for (int mt = 0; mt < 2; mt++) {
                    unsigned a0 = ((const unsigned*)&a0f[mt][0][0])[kk];
                    unsigned a1 = ((const unsigned*)&a0f[mt][1][0])[kk];
                    unsigned a2 = ((const unsigned*)&a0f[mt][0][1])[kk];
                    unsigned a3 = ((const unsigned*)&a0f[mt][1][1])[kk];
                    #pragma unroll
                    for (int i = 0; i < 4; i++) {
                        int nt = ng * 4 + i;
                        mma16816(acc[mt][nt][0], acc[mt][nt][1],
                                 acc[mt][nt][2], acc[mt][nt][3],
                                 a0, a1, a2, a3,
                                 ((const unsigned*)&bp[i][0])[kk],
                                 ((const unsigned*)&bp[i][1])[kk]);
                    }
                }
        }

        // ---- epilogue: scores, per-ctx fmax tree, rare indexed rescan ----
        int jt = t * 128;
        float2 hnv[8];
        #pragma unroll
        for (int nt = 0; nt < 8; nt++)
            hnv[nt] = hn2p[(jt >> 1) + wn * 32 + nt * 4 + cfr];
        #pragma unroll
        for (int nt = 0; nt < 8; nt++)
            #pragma unroll
            for (int mt = 0; mt < 2; mt++) {
                acc[mt][nt][0] -= hnv[nt].x;
                acc[mt][nt][1] -= hnv[nt].y;
                acc[mt][nt][2] -= hnv[nt].x;
                acc[mt][nt][3] -= hnv[nt].y;
            }
        #pragma unroll
        for (int mt = 0; mt < 2; mt++)
            #pragma unroll
            for (int rr = 0; rr < 2; rr++) {
                int ctx = mt * 2 + rr;
                float sv[16];
                #pragma unroll
                for (int la = 0; la < 16; la++)
                    sv[la] = acc[mt][la >> 1][rr * 2 + (la & 1)];
                float m = sv[0];
                #pragma unroll
                for (int st = 8; st; st >>= 1)
                    #pragma unroll
                    for (int i = 0; i < st; i++)
                        sv[i] = fmaxf(sv[i], sv[i + st]);
                m = sv[0];
                if (m > rb2[ctx]) {
                    int la = 0;
                    #pragma unroll
                    for (int i = 15; i >= 0; i--)
                        if (acc[mt][i >> 1][rr * 2 + (i & 1)] == m) la = i;
                    int jarg = jt + wn * 64 + (la >> 1) * 8 + cfr * 2 + (la & 1);
                    if (m > rb1[ctx]) {
                        rb2[ctx] = rb1[ctx]; ri2[ctx] = ri1[ctx];
                        rb1[ctx] = m; ri1[ctx] = jarg;
                    } else { rb2[ctx] = m; ri2[ctx] = jarg; }
                }
            }
        __syncthreads();   // all warps done reading buf t before it is refilled
    }

    // merge top-2 across the 4 lanes (cfr groups) sharing each row
    #pragma unroll
    for (int ctx = 0; ctx < 4; ctx++) {
        #pragma unroll
        for (int m = 1; m <= 2; m <<= 1) {
            float ob1 = __shfl_xor_sync(0xffffffffu, rb1[ctx], m);
            int   oi1 = __shfl_xor_sync(0xffffffffu, ri1[ctx], m);
            float ob2 = __shfl_xor_sync(0xffffffffu, rb2[ctx], m);
            int   oi2 = __shfl_xor_sync(0xffffffffu, ri2[ctx], m);
            if (rank_gt(ob1, oi1, rb1[ctx], ri1[ctx])) {
                if (rank_gt(rb1[ctx], ri1[ctx], ob2, oi2)) {
                    rb2[ctx] = rb1[ctx]; ri2[ctx] = ri1[ctx];
                } else { rb2[ctx] = ob2; ri2[ctx] = oi2; }
                rb1[ctx] = ob1; ri1[ctx] = oi1;
            } else if (rank_gt(ob1, oi1, rb2[ctx], ri2[ctx])) {
                rb2[ctx] = ob1; ri2[ctx] = oi1;
            }
        }
    }
    // each wn-warp writes ITS j-half's top-2 into its own int2 slot
    if (cfr == 0) {
        #pragma unroll
        for (int ctx = 0; ctx < 4; ctx++) {
            int mt = ctx >> 1, rr = ctx & 1;
            int m_local = wm * 32 + mt * 16 + rr * 8 + tu;
            int qc = tile_m * 128 + m_local;
            if (qc < MC) {
                int py = cls >> 1, px = cls & 1;
                int a = qc / NC, b = qc - a * NC;
                int q = (py + 2 * a) * L1 + (px + 2 * b);
                int2 cd; cd.x = ri1[ctx]; cd.y = ri2[ctx];
                ((int2*)&g_cand4[q])[wn] = cd;
            }
        }
    }
}

// ---------------------------------------------------------------------------
// Repair: exact fp32 evaluation of the 4 candidates per query (top-2 from
// each j-half); semantics identical to the R4 kernel, which matched the
// reference argmin bit-for-bit.
// ---------------------------------------------------------------------------
__global__ void repair(const float* __restrict__ image) {
    int q = blockIdx.x * 256 + threadIdx.x;
    if (q >= MQ) return;
    int4 cd = g_cand4[q];
    int cands[4] = {cd.x, cd.y, cd.z, cd.w};
    int r = q / L1, c = q - r * L1;
    int cls = (r & 1) * 2 + (c & 1);
    int by = (r - PAD) >> 1, bx = (c - PAD) >> 1;
    float x[KC];
    #pragma unroll
    for (int s = 0; s < KC; s++) {
        int sy = s >> 3, sx = s & 7;
        int yy = by + sy, xx = bx + sx;
        x[s] = ((unsigned)yy < 64u && (unsigned)xx < 64u)
                   ? image[yy * 64 + xx] : 0.f;
    }
    float best = 3.4e38f; int bi = 0x7fffffff;
    #pragma unroll
    for (int ci = 0; ci < 4; ci++) {
        int cj = cands[ci];
        const float* mm = g_m2f + ((size_t)(cls * NMEM + cj) << 6);
        float d = 0.f;
        #pragma unroll
        for (int s = 0; s < KC; s++) d += x[s] * mm[s];
        d = g_norms[cj] - d;          // 0.5*(|m|^2 - 2 x.m)
        if (d < best || (d == best && cj < bi)) { best = d; bi = cj; }
    }
    g_idx[q] = bi;
}

// ---------------------------------------------------------------------------
// Reconstruction: out_raw[a][b] = acc[2a+10][2b+10]
// ---------------------------------------------------------------------------
__global__ void recon(const float* __restrict__ mem) {
    int t = blockIdx.x * 256 + threadIdx.x;      // 0..4095
    if (t >= 4096) return;
    int a = t >> 6, b = t & 63;
    int y = 2 * a + PAD, x = 2 * b + PAD;
    float s = 0.f;
    #pragma unroll
    for (int i = 0; i < KSZ; i++) {
        int ry = y - i;
        if ((unsigned)ry >= (unsigned)L1) continue;
        int rowbase = ry * L1;
        #pragma unroll
        for (int j = 0; j < KSZ; j++) {
            int rx = x - j;
            if ((unsigned)rx >= (unsigned)L1) continue;
            s += mem[g_idx[rowbase + rx] * KDIM + i * KSZ + j];
        }
    }
    g_raw[t] = s;
}

// max-normalize (single block)
__global__ void normalize_out(float* __restrict__ out) {
    __shared__ float smx[256];
    int tid = threadIdx.x;
    float mx = -3.4e38f;
    for (int i = tid; i < 4096; i += 256) mx = fmaxf(mx, g_raw[i]);
    smx[tid] = mx;
    __syncthreads();
    for (int o = 128; o; o >>= 1) {
        if (tid < o) smx[tid] = fmaxf(smx[tid], smx[tid + o]);
        __syncthreads();
    }
    float m = smx[0];
    for (int i = tid; i < 4096; i += 256) out[i] = g_raw[i] / m;
}

// ---------------------------------------------------------------------------
extern "C" void kernel_launch(void* const* d_in, const int* in_sizes, int n_in,
                              void* d_out, int out_size) {
    const float* image = (const float*)d_in[0];   // 64*64
    const float* mem   = (const float*)d_in[1];   // 16384*225
    float* out = (float*)d_out;                   // 64*64

    cudaFuncSetAttribute(gemm_argmin,
                         cudaFuncAttributeMaxDynamicSharedMemorySize,
                         GEMM_SMEM);

    {
        int n = 4 * BPC * 128 * 32;
        prep_Ah<<<(n + 255) / 256, 256>>>(image);
    }
    {
        int n = 4 * NMEM * 32;
        prep_Bh<<<(n + 255) / 256, 256>>>(mem);
    }
    prep_norms<<<(NMEM * 32) / 256, 256>>>(mem);

    gemm_argmin<<<GEMM_BLOCKS, GEMM_THREADS, GEMM_SMEM>>>();

    repair<<<(MQ + 255) / 256, 256>>>(image);
    recon<<<16, 256>>>(mem);
    normalize_out<<<1, 256>>>(out);
}